// round 14
// baseline (speedup 1.0000x reference)
#include <cuda_runtime.h>

typedef unsigned long long ull;

__device__ __forceinline__ ull pack2(float lo, float hi) {
    ull r; asm("mov.b64 %0, {%1, %2};" : "=l"(r) : "f"(lo), "f"(hi)); return r;
}
__device__ __forceinline__ void unpack2(ull v, float& lo, float& hi) {
    asm("mov.b64 {%0, %1}, %2;" : "=f"(lo), "=f"(hi) : "l"(v));
}
__device__ __forceinline__ void fma2(ull& d, ull a, ull b) {
    asm("fma.rn.f32x2 %0, %1, %2, %0;" : "+l"(d) : "l"(a), "l"(b));
}
__device__ __forceinline__ ull mul2(ull a, ull b) {
    ull r; asm("mul.rn.f32x2 %0, %1, %2;" : "=l"(r) : "l"(a), "l"(b)); return r;
}
__device__ __forceinline__ void add2(ull& d, ull a) {
    asm("add.rn.f32x2 %0, %0, %1;" : "+l"(d) : "l"(a));
}
__device__ __forceinline__ float ex2f(float x) {
    float y; asm("ex2.approx.f32 %0, %1;" : "=f"(y) : "f"(x)); return y;
}

// ---------------- scratch (no allocations allowed) ----------------
#define NTOK (2*4096)              // 8192 tokens
#define PBUF (NTOK*64)             // 524288 floats per partial buffer
__device__ float g_p[4*PBUF];      // conv1 partials (per ci-quarter)
__device__ float g_q[4*PBUF];      // conv2 partials (per ci-quarter)
__device__ float g_wt1[64*9*64];   // [ci][k][(co2,s)]: pair = (co2, co2+32)
__device__ float g_wt2[64*9*64];

// ---- prep: [co][ci][3][3] -> [ci][k][(co2,s)] where pair = (co2, co2+32) ----
__global__ void k_transpose_w(const float* __restrict__ w1, const float* __restrict__ w2) {
    int i = blockIdx.x * blockDim.x + threadIdx.x;
    if (i >= 2 * 36864) return;
    const float* w = (i < 36864) ? w1 : w2;
    float* dst     = (i < 36864) ? g_wt1 : g_wt2;
    int o   = (i < 36864) ? i : (i - 36864);
    int ci  = o / 576;
    int rem = o - ci * 576;
    int kk  = rem >> 6;
    int qq  = rem & 63;
    int co2 = qq >> 1;
    int s   = qq & 1;
    dst[o] = w[(s * 32 + co2) * 576 + ci * 9 + kk];
}

// ---------------- partial conv3x3: 16 ci x 64 co per block (R11, unchanged) ------
#define IN_CI_STRIDE 148
template<int SRC>
__global__ void __launch_bounds__(256, 3) k_conv(const float* __restrict__ in_x,
                                                 const float* __restrict__ in_bias) {
    const float* __restrict__ wt = (SRC == 0) ? g_wt1 : g_wt2;

    __shared__ float w_s[16 * 576];
    __shared__ float in_s[16 * IN_CI_STRIDE];

    const int tid = threadIdx.x;
    const int co2 = tid & 31;
    const int h   = tid >> 5;
    const int x0 = blockIdx.x * 32, y0 = blockIdx.y * 2;
    const int b       = blockIdx.z >> 2;
    const int quarter = blockIdx.z & 3;

    {
        const float4* wsrc = (const float4*)(wt + quarter * 16 * 576);
        float4* wdst = (float4*)w_s;
#pragma unroll
        for (int i = 0; i < 9; i++)
            wdst[tid + i * 256] = wsrc[tid + i * 256];
    }
    if (SRC == 0) {
#pragma unroll
        for (int i = 0; i < 9; i++) {
            int e = i * 256 + tid;
            if (e < 2176) {
                int xx = e % 34;
                int t  = e / 34;
                int r  = t & 3;
                int ci = t >> 2;
                int y  = y0 - 1 + r;
                int xg = x0 - 1 + xx;
                float v = 0.f;
                if ((unsigned)y < 64u && (unsigned)xg < 64u)
                    v = in_x[((b * 64 + quarter * 16 + ci) * 64 + y) * 64 + xg];
                in_s[ci * IN_CI_STRIDE + r * 36 + xx] = v;
            }
        }
    } else {
        const int ci = tid & 15;
        const float bvin = in_bias[quarter * 16 + ci];
#pragma unroll
        for (int i = 0; i < 9; i++) {
            int e = i * 256 + tid;
            if (e < 2176) {
                int t  = e >> 4;
                int r  = t / 34;
                int xx = t - r * 34;
                int y  = y0 - 1 + r;
                int xg = x0 - 1 + xx;
                float v = 0.f;
                if ((unsigned)y < 64u && (unsigned)xg < 64u) {
                    int idx = ((b * 64 + y) * 64 + xg) * 64 + quarter * 16 + ci;
                    float s0 = g_p[idx]          + g_p[idx + PBUF];
                    float s1 = g_p[idx + 2*PBUF] + g_p[idx + 3*PBUF];
                    v = fmaxf(s0 + s1 + bvin, 0.f);
                }
                in_s[ci * IN_CI_STRIDE + r * 36 + xx] = v;
            }
        }
    }
    __syncthreads();

    ull accA[4] = {0,0,0,0};
    ull accB[4] = {0,0,0,0};

#pragma unroll 4
    for (int ci = 0; ci < 16; ci++) {
        const ull* wp = (const ull*)(w_s + ci * 576) + co2;
        ull w2[9];
#pragma unroll
        for (int k = 0; k < 9; k++) w2[k] = wp[k * 32];

        const float* ibase = in_s + ci * IN_CI_STRIDE + h * 4;
#pragma unroll
        for (int irow = 0; irow < 4; irow++) {
            float4 v0 = *(const float4*)(ibase + irow * 36);
            float2 v1 = *(const float2*)(ibase + irow * 36 + 4);
            ull d[6];
            d[0] = pack2(v0.x, v0.x); d[1] = pack2(v0.y, v0.y);
            d[2] = pack2(v0.z, v0.z); d[3] = pack2(v0.w, v0.w);
            d[4] = pack2(v1.x, v1.x); d[5] = pack2(v1.y, v1.y);
            if (irow < 3) {
#pragma unroll
                for (int p = 0; p < 4; p++) {
                    fma2(accA[p], w2[irow*3+0], d[p]);
                    fma2(accA[p], w2[irow*3+1], d[p+1]);
                    fma2(accA[p], w2[irow*3+2], d[p+2]);
                }
            }
            if (irow >= 1) {
#pragma unroll
                for (int p = 0; p < 4; p++) {
                    fma2(accB[p], w2[(irow-1)*3+0], d[p]);
                    fma2(accB[p], w2[(irow-1)*3+1], d[p+1]);
                    fma2(accB[p], w2[(irow-1)*3+2], d[p+2]);
                }
            }
        }
    }

    float* __restrict__ out = ((SRC == 0) ? g_p : g_q) + quarter * PBUF;
    int base = ((b * 64 + y0) * 64 + x0 + h * 4) * 64;
#pragma unroll
    for (int p = 0; p < 4; p++) {
        float a0, a1, b0v, b1v;
        unpack2(accA[p], a0, a1);
        unpack2(accB[p], b0v, b1v);
        out[base + p * 64 + co2]             = a0;
        out[base + p * 64 + co2 + 32]        = a1;
        out[base + 4096 + p * 64 + co2]      = b0v;
        out[base + 4096 + p * 64 + co2 + 32] = b1v;
    }
}

// ---------------- attention: 32 tokens/block, 512 threads, fused, 3 barriers ------
// mapping: tt = tid & 31 (token = lane), cg = tid >> 5 (warp, 0..15), 4 ch/thread.
#define W_STRIDE 68                // 16B-aligned rows -> LDS.128 weight reads
#define OFF_WQ 0
#define OFF_WK 4352
#define OFF_WV 8704
#define OFF_WO 13056
#define OFF_T  17408               // [32][65]
#define OFF_KV 19488               // float2 [32][66]  (16B aligned)
#define OFF_O  23712               // [32][65]
#define OFF_SQ 25792               // [16][33]
#define OFF_SK 26320
#define SMEM_FLOATS 26848          // 107392 bytes

__global__ void __launch_bounds__(512, 2) k_attn(
    const float* __restrict__ wq, const float* __restrict__ wk,
    const float* __restrict__ wv, const float* __restrict__ wo,
    const float* __restrict__ bo, const float* __restrict__ b2,
    float* __restrict__ out)
{
    extern __shared__ float sm[];
    float*  wq_s = sm + OFF_WQ;    // [l][c], stride 68
    float*  wk_s = sm + OFF_WK;
    float*  wv_s = sm + OFF_WV;
    float*  wo_s = sm + OFF_WO;
    float*  t_s  = sm + OFF_T;
    float2* kv_s = (float2*)(sm + OFF_KV);   // [32][66], raw {k, v}
    float*  o_s  = sm + OFF_O;
    float*  sq_s = sm + OFF_SQ;
    float*  sk_s = sm + OFF_SK;

    int tid = threadIdx.x;
    int n0  = blockIdx.x * 32;

    // stage weights transposed via float4 LDG (coalesced) + 4 scalar STS
#pragma unroll
    for (int i = 0; i < 2; i++) {
        int g4 = tid + i * 512;        // float4 index, 0..1023
        int c  = g4 >> 4;
        int l0 = (g4 & 15) * 4;
        float4 a = ((const float4*)wq)[g4];
        float4 b = ((const float4*)wk)[g4];
        float4 cc = ((const float4*)wv)[g4];
        float4 d = ((const float4*)wo)[g4];
        wq_s[(l0+0)*W_STRIDE+c]=a.x; wq_s[(l0+1)*W_STRIDE+c]=a.y;
        wq_s[(l0+2)*W_STRIDE+c]=a.z; wq_s[(l0+3)*W_STRIDE+c]=a.w;
        wk_s[(l0+0)*W_STRIDE+c]=b.x; wk_s[(l0+1)*W_STRIDE+c]=b.y;
        wk_s[(l0+2)*W_STRIDE+c]=b.z; wk_s[(l0+3)*W_STRIDE+c]=b.w;
        wv_s[(l0+0)*W_STRIDE+c]=cc.x; wv_s[(l0+1)*W_STRIDE+c]=cc.y;
        wv_s[(l0+2)*W_STRIDE+c]=cc.z; wv_s[(l0+3)*W_STRIDE+c]=cc.w;
        wo_s[(l0+0)*W_STRIDE+c]=d.x; wo_s[(l0+1)*W_STRIDE+c]=d.y;
        wo_s[(l0+2)*W_STRIDE+c]=d.z; wo_s[(l0+3)*W_STRIDE+c]=d.w;
    }
    // t = Σ4 conv2 partials + b2
#pragma unroll
    for (int i = 0; i < 4; i++) {
        int gg = tid + i * 512;
        int idx = n0 * 64 + gg;
        float s0 = g_q[idx]          + g_q[idx + PBUF];
        float s1 = g_q[idx + 2*PBUF] + g_q[idx + 3*PBUF];
        t_s[(gg >> 6) * 65 + (gg & 63)] = s0 + s1 + b2[gg & 63];
    }
    __syncthreads();                                   // B1

    const int tt = tid & 31;
    const int cg = tid >> 5;
    const int c0 = cg * 4;

    // phase 1: q/k/v matvecs (LDS.128 weight reads)
    ull q2[2] = {0,0}, k2[2] = {0,0}, v2[2] = {0,0};
    const float* trow = t_s + tt * 65;
#pragma unroll 4
    for (int l = 0; l < 64; l++) {
        float tl = trow[l];
        ull tl2 = pack2(tl, tl);
        ulonglong2 a = *(const ulonglong2*)(wq_s + l * W_STRIDE + c0);
        ulonglong2 b = *(const ulonglong2*)(wk_s + l * W_STRIDE + c0);
        ulonglong2 c = *(const ulonglong2*)(wv_s + l * W_STRIDE + c0);
        fma2(q2[0], tl2, a.x); fma2(q2[1], tl2, a.y);
        fma2(k2[0], tl2, b.x); fma2(k2[1], tl2, b.y);
        fma2(v2[0], tl2, c.x); fma2(v2[1], tl2, c.y);
    }
    float q[4], kk[4], vv[4];
    unpack2(q2[0], q[0], q[1]);  unpack2(q2[1], q[2], q[3]);
    unpack2(k2[0], kk[0], kk[1]); unpack2(k2[1], kk[2], kk[3]);
    unpack2(v2[0], vv[0], vv[1]); unpack2(v2[1], vv[2], vv[3]);

    // raw k,v to smem (one float4 = 2 float2 slots); norm partials
    *(float4*)(kv_s + tt * 66 + c0)     = make_float4(kk[0], vv[0], kk[1], vv[1]);
    *(float4*)(kv_s + tt * 66 + c0 + 2) = make_float4(kk[2], vv[2], kk[3], vv[3]);
    float sq = 0.f, sk = 0.f;
#pragma unroll
    for (int j = 0; j < 4; j++) { sq = fmaf(q[j], q[j], sq); sk = fmaf(kk[j], kk[j], sk); }
    sq_s[cg * 33 + tt] = sq;
    sk_s[cg * 33 + tt] = sk;
    __syncthreads();                                   // B2

    sq = 0.f; sk = 0.f;
#pragma unroll
    for (int m = 0; m < 16; m++) { sq += sq_s[m * 33 + tt]; sk += sk_s[m * 33 + tt]; }
    const float LOG2E = 1.4426950408889634f;
    // fold invq * invk * log2(e) into q; k stays raw
    float scale = __fdividef(LOG2E,
                             fmaxf(sqrtf(sq), 1e-12f) * fmaxf(sqrtf(sk), 1e-12f));
    ull qq[4];
#pragma unroll
    for (int j = 0; j < 4; j++) {
        float qs = q[j] * scale;
        qq[j] = pack2(qs, qs);
    }

    // phase 2: 2 d's per iter; packed {even,odd} num/den accumulators
    ull num[4] = {0,0,0,0}, den[4] = {0,0,0,0};
    const float4* kv4 = (const float4*)(kv_s + tt * 66);   // {kd0,vd0,kd1,vd1}
#pragma unroll 4
    for (int dd = 0; dd < 32; dd++) {
        float4 f = kv4[dd];
        ull kpair = pack2(f.x, f.z);
        ull vpair = pack2(f.y, f.w);
#pragma unroll
        for (int j = 0; j < 4; j++) {
            ull p = mul2(qq[j], kpair);
            float p0, p1;
            unpack2(p, p0, p1);
            ull e = pack2(ex2f(p0), ex2f(p1));
            fma2(num[j], e, vpair);
            add2(den[j], e);
        }
    }
#pragma unroll
    for (int j = 0; j < 4; j++) {
        float na, nb, da, db;
        unpack2(num[j], na, nb);
        unpack2(den[j], da, db);
        o_s[tt * 65 + c0 + j] = __fdividef(na + nb, da + db);
    }
    __syncthreads();                                   // B3

    // phase 3: Wo projection + bias + residual; coalesced NCHW stores
    ull fin2[2] = {0,0};
    const float* orow = o_s + tt * 65;
#pragma unroll 4
    for (int c = 0; c < 64; c++) {
        float oc = orow[c];
        ull oc2 = pack2(oc, oc);
        ulonglong2 w = *(const ulonglong2*)(wo_s + c * W_STRIDE + c0);
        fma2(fin2[0], oc2, w.x);
        fma2(fin2[1], oc2, w.y);
    }
    int b = n0 >> 12;
    int s = (n0 & 4095) + tt;
#pragma unroll
    for (int j = 0; j < 2; j++) {
        float f0, f1;
        unpack2(fin2[j], f0, f1);
        int ch = c0 + 2 * j;
        f0 += bo[ch]     + t_s[tt * 65 + ch];
        f1 += bo[ch + 1] + t_s[tt * 65 + ch + 1];
        out[(b * 64 + ch    ) * 4096 + s] = f0;
        out[(b * 64 + ch + 1) * 4096 + s] = f1;
    }
}

// ---------------- launch ----------------
extern "C" void kernel_launch(void* const* d_in, const int* in_sizes, int n_in,
                              void* d_out, int out_size) {
    const float* x  = (const float*)d_in[0];
    const float* w1 = (const float*)d_in[1];
    const float* b1 = (const float*)d_in[2];
    const float* w2 = (const float*)d_in[3];
    const float* b2 = (const float*)d_in[4];
    const float* wq = (const float*)d_in[5];
    const float* wk = (const float*)d_in[6];
    const float* wv = (const float*)d_in[7];
    const float* wo = (const float*)d_in[8];
    const float* bo = (const float*)d_in[9];
    float* out = (float*)d_out;

    cudaFuncSetAttribute(k_attn, cudaFuncAttributeMaxDynamicSharedMemorySize,
                         SMEM_FLOATS * (int)sizeof(float));

    k_transpose_w<<<(2 * 36864 + 255) / 256, 256>>>(w1, w2);
    k_conv<0><<<dim3(2, 32, 8), dim3(256)>>>(x, b1);
    k_conv<1><<<dim3(2, 32, 8), dim3(256)>>>(x, b1);
    k_attn<<<256, 512, SMEM_FLOATS * (int)sizeof(float)>>>(wq, wk, wv, wo, bo, b2, out);
}

// round 15
// speedup vs baseline: 1.0617x; 1.0617x over previous
#include <cuda_runtime.h>

typedef unsigned long long ull;

__device__ __forceinline__ ull pack2(float lo, float hi) {
    ull r; asm("mov.b64 %0, {%1, %2};" : "=l"(r) : "f"(lo), "f"(hi)); return r;
}
__device__ __forceinline__ void unpack2(ull v, float& lo, float& hi) {
    asm("mov.b64 {%0, %1}, %2;" : "=f"(lo), "=f"(hi) : "l"(v));
}
__device__ __forceinline__ void fma2(ull& d, ull a, ull b) {
    asm("fma.rn.f32x2 %0, %1, %2, %0;" : "+l"(d) : "l"(a), "l"(b));
}
__device__ __forceinline__ float ex2f(float x) {
    float y; asm("ex2.approx.f32 %0, %1;" : "=f"(y) : "f"(x)); return y;
}

// ---------------- scratch (no allocations allowed) ----------------
#define NTOK (2*4096)              // 8192 tokens
#define PBUF (NTOK*64)             // 524288 floats per partial buffer
__device__ float g_p[4*PBUF];      // conv1 partials (per ci-quarter)
__device__ float g_q[4*PBUF];      // conv2 partials (per ci-quarter)
__device__ float g_wt1[64*9*64];   // [ci][k][(co2,s)]: pair = (co2, co2+32)
__device__ float g_wt2[64*9*64];

// ---- prep: [co][ci][3][3] -> [ci][k][(co2,s)] where pair = (co2, co2+32) ----
__global__ void k_transpose_w(const float* __restrict__ w1, const float* __restrict__ w2) {
    int i = blockIdx.x * blockDim.x + threadIdx.x;
    if (i >= 2 * 36864) return;
    const float* w = (i < 36864) ? w1 : w2;
    float* dst     = (i < 36864) ? g_wt1 : g_wt2;
    int o   = (i < 36864) ? i : (i - 36864);
    int ci  = o / 576;
    int rem = o - ci * 576;
    int kk  = rem >> 6;
    int qq  = rem & 63;
    int co2 = qq >> 1;
    int s   = qq & 1;
    dst[o] = w[(s * 32 + co2) * 576 + ci * 9 + kk];
}

// ---------------- partial conv3x3: 16 ci x 64 co per block (R11, unchanged) ------
#define IN_CI_STRIDE 148
template<int SRC>
__global__ void __launch_bounds__(256, 3) k_conv(const float* __restrict__ in_x,
                                                 const float* __restrict__ in_bias) {
    const float* __restrict__ wt = (SRC == 0) ? g_wt1 : g_wt2;

    __shared__ float w_s[16 * 576];
    __shared__ float in_s[16 * IN_CI_STRIDE];

    const int tid = threadIdx.x;
    const int co2 = tid & 31;
    const int h   = tid >> 5;
    const int x0 = blockIdx.x * 32, y0 = blockIdx.y * 2;
    const int b       = blockIdx.z >> 2;
    const int quarter = blockIdx.z & 3;

    {
        const float4* wsrc = (const float4*)(wt + quarter * 16 * 576);
        float4* wdst = (float4*)w_s;
#pragma unroll
        for (int i = 0; i < 9; i++)
            wdst[tid + i * 256] = wsrc[tid + i * 256];
    }
    if (SRC == 0) {
#pragma unroll
        for (int i = 0; i < 9; i++) {
            int e = i * 256 + tid;
            if (e < 2176) {
                int xx = e % 34;
                int t  = e / 34;
                int r  = t & 3;
                int ci = t >> 2;
                int y  = y0 - 1 + r;
                int xg = x0 - 1 + xx;
                float v = 0.f;
                if ((unsigned)y < 64u && (unsigned)xg < 64u)
                    v = in_x[((b * 64 + quarter * 16 + ci) * 64 + y) * 64 + xg];
                in_s[ci * IN_CI_STRIDE + r * 36 + xx] = v;
            }
        }
    } else {
        const int ci = tid & 15;
        const float bvin = in_bias[quarter * 16 + ci];
#pragma unroll
        for (int i = 0; i < 9; i++) {
            int e = i * 256 + tid;
            if (e < 2176) {
                int t  = e >> 4;
                int r  = t / 34;
                int xx = t - r * 34;
                int y  = y0 - 1 + r;
                int xg = x0 - 1 + xx;
                float v = 0.f;
                if ((unsigned)y < 64u && (unsigned)xg < 64u) {
                    int idx = ((b * 64 + y) * 64 + xg) * 64 + quarter * 16 + ci;
                    float s0 = g_p[idx]          + g_p[idx + PBUF];
                    float s1 = g_p[idx + 2*PBUF] + g_p[idx + 3*PBUF];
                    v = fmaxf(s0 + s1 + bvin, 0.f);
                }
                in_s[ci * IN_CI_STRIDE + r * 36 + xx] = v;
            }
        }
    }
    __syncthreads();

    ull accA[4] = {0,0,0,0};
    ull accB[4] = {0,0,0,0};

#pragma unroll 4
    for (int ci = 0; ci < 16; ci++) {
        const ull* wp = (const ull*)(w_s + ci * 576) + co2;
        ull w2[9];
#pragma unroll
        for (int k = 0; k < 9; k++) w2[k] = wp[k * 32];

        const float* ibase = in_s + ci * IN_CI_STRIDE + h * 4;
#pragma unroll
        for (int irow = 0; irow < 4; irow++) {
            float4 v0 = *(const float4*)(ibase + irow * 36);
            float2 v1 = *(const float2*)(ibase + irow * 36 + 4);
            ull d[6];
            d[0] = pack2(v0.x, v0.x); d[1] = pack2(v0.y, v0.y);
            d[2] = pack2(v0.z, v0.z); d[3] = pack2(v0.w, v0.w);
            d[4] = pack2(v1.x, v1.x); d[5] = pack2(v1.y, v1.y);
            if (irow < 3) {
#pragma unroll
                for (int p = 0; p < 4; p++) {
                    fma2(accA[p], w2[irow*3+0], d[p]);
                    fma2(accA[p], w2[irow*3+1], d[p+1]);
                    fma2(accA[p], w2[irow*3+2], d[p+2]);
                }
            }
            if (irow >= 1) {
#pragma unroll
                for (int p = 0; p < 4; p++) {
                    fma2(accB[p], w2[(irow-1)*3+0], d[p]);
                    fma2(accB[p], w2[(irow-1)*3+1], d[p+1]);
                    fma2(accB[p], w2[(irow-1)*3+2], d[p+2]);
                }
            }
        }
    }

    float* __restrict__ out = ((SRC == 0) ? g_p : g_q) + quarter * PBUF;
    int base = ((b * 64 + y0) * 64 + x0 + h * 4) * 64;
#pragma unroll
    for (int p = 0; p < 4; p++) {
        float a0, a1, b0v, b1v;
        unpack2(accA[p], a0, a1);
        unpack2(accB[p], b0v, b1v);
        out[base + p * 64 + co2]             = a0;
        out[base + p * 64 + co2 + 32]        = a1;
        out[base + 4096 + p * 64 + co2]      = b0v;
        out[base + 4096 + p * 64 + co2 + 32] = b1v;
    }
}

// ---------------- attention: 32 tokens/block, 512 threads, fused, 3 barriers ------
// mapping: tt = tid & 31 (token = lane), cg = tid >> 5 (warp, 0..15), 4 ch/thread.
#define W_STRIDE 68                // 16B-aligned rows -> LDS.128 weight reads
#define OFF_WQ 0
#define OFF_WK 4352
#define OFF_WV 8704
#define OFF_WO 13056
#define OFF_T  17408               // [32][65]
#define OFF_KV 19488               // float2 [32][65] (stride 65: conflict-free LDS.64)
#define OFF_O  23648               // [32][65]
#define OFF_SQ 25728               // [16][33]
#define OFF_SK 26256
#define SMEM_FLOATS 26784          // 107136 bytes

__global__ void __launch_bounds__(512, 2) k_attn(
    const float* __restrict__ wq, const float* __restrict__ wk,
    const float* __restrict__ wv, const float* __restrict__ wo,
    const float* __restrict__ bo, const float* __restrict__ b2,
    float* __restrict__ out)
{
    extern __shared__ float sm[];
    float*  wq_s = sm + OFF_WQ;    // [l][c], stride 68
    float*  wk_s = sm + OFF_WK;
    float*  wv_s = sm + OFF_WV;
    float*  wo_s = sm + OFF_WO;
    float*  t_s  = sm + OFF_T;
    float2* kv_s = (float2*)(sm + OFF_KV);   // [32][65], raw {k, v}
    float*  o_s  = sm + OFF_O;
    float*  sq_s = sm + OFF_SQ;
    float*  sk_s = sm + OFF_SK;

    int tid = threadIdx.x;
    int n0  = blockIdx.x * 32;

    // stage weights transposed (coalesced scalar LDG, STS to stride-68 rows)
#pragma unroll
    for (int i = 0; i < 8; i++) {
        int gg = tid + i * 512;
        int c = gg >> 6, l = gg & 63;
        wq_s[l * W_STRIDE + c] = wq[gg];
        wk_s[l * W_STRIDE + c] = wk[gg];
        wv_s[l * W_STRIDE + c] = wv[gg];
        wo_s[l * W_STRIDE + c] = wo[gg];
    }
    // t = Σ4 conv2 partials + b2
#pragma unroll
    for (int i = 0; i < 4; i++) {
        int gg = tid + i * 512;
        int idx = n0 * 64 + gg;
        float s0 = g_q[idx]          + g_q[idx + PBUF];
        float s1 = g_q[idx + 2*PBUF] + g_q[idx + 3*PBUF];
        t_s[(gg >> 6) * 65 + (gg & 63)] = s0 + s1 + b2[gg & 63];
    }
    __syncthreads();                                   // B1

    const int tt = tid & 31;
    const int cg = tid >> 5;
    const int c0 = cg * 4;

    // phase 1: q/k/v matvecs (LDS.128 broadcast weight reads)
    ull q2[2] = {0,0}, k2[2] = {0,0}, v2[2] = {0,0};
    const float* trow = t_s + tt * 65;
#pragma unroll 4
    for (int l = 0; l < 64; l++) {
        float tl = trow[l];
        ull tl2 = pack2(tl, tl);
        ulonglong2 a = *(const ulonglong2*)(wq_s + l * W_STRIDE + c0);
        ulonglong2 b = *(const ulonglong2*)(wk_s + l * W_STRIDE + c0);
        ulonglong2 c = *(const ulonglong2*)(wv_s + l * W_STRIDE + c0);
        fma2(q2[0], tl2, a.x); fma2(q2[1], tl2, a.y);
        fma2(k2[0], tl2, b.x); fma2(k2[1], tl2, b.y);
        fma2(v2[0], tl2, c.x); fma2(v2[1], tl2, c.y);
    }
    float q[4], kk[4], vv[4];
    unpack2(q2[0], q[0], q[1]);  unpack2(q2[1], q[2], q[3]);
    unpack2(k2[0], kk[0], kk[1]); unpack2(k2[1], kk[2], kk[3]);
    unpack2(v2[0], vv[0], vv[1]); unpack2(v2[1], vv[2], vv[3]);

    // raw k,v to smem (stride-65 rows: conflict-free later reads); norm partials
#pragma unroll
    for (int j = 0; j < 4; j++)
        kv_s[tt * 65 + c0 + j] = make_float2(kk[j], vv[j]);
    float sq = 0.f, sk = 0.f;
#pragma unroll
    for (int j = 0; j < 4; j++) { sq = fmaf(q[j], q[j], sq); sk = fmaf(kk[j], kk[j], sk); }
    sq_s[cg * 33 + tt] = sq;
    sk_s[cg * 33 + tt] = sk;
    __syncthreads();                                   // B2

    sq = 0.f; sk = 0.f;
#pragma unroll
    for (int m = 0; m < 16; m++) { sq += sq_s[m * 33 + tt]; sk += sk_s[m * 33 + tt]; }
    const float LOG2E = 1.4426950408889634f;
    // fold invq * invk * log2(e) into q; k stays raw in smem
    float scale = __fdividef(LOG2E,
                             fmaxf(sqrtf(sq), 1e-12f) * fmaxf(sqrtf(sk), 1e-12f));
    float qs[4];
#pragma unroll
    for (int j = 0; j < 4; j++) qs[j] = q[j] * scale;

    // phase 2: rank-1 softmax; packed num/den: fma2(nd, {e,e}, {v_d, 1})
    ull nd[4] = {0,0,0,0};
    const float2* kvrow = kv_s + tt * 65;
#pragma unroll 4
    for (int d = 0; d < 64; d++) {
        float2 kv = kvrow[d];
        ull vd2 = pack2(kv.y, 1.0f);
#pragma unroll
        for (int j = 0; j < 4; j++) {
            float e = ex2f(qs[j] * kv.x);
            fma2(nd[j], pack2(e, e), vd2);
        }
    }
#pragma unroll
    for (int j = 0; j < 4; j++) {
        float num, den;
        unpack2(nd[j], num, den);
        o_s[tt * 65 + c0 + j] = __fdividef(num, den);
    }
    __syncthreads();                                   // B3

    // phase 3: Wo projection + bias + residual; coalesced NCHW stores
    ull fin2[2] = {0,0};
    const float* orow = o_s + tt * 65;
#pragma unroll 4
    for (int c = 0; c < 64; c++) {
        float oc = orow[c];
        ull oc2 = pack2(oc, oc);
        ulonglong2 w = *(const ulonglong2*)(wo_s + c * W_STRIDE + c0);
        fma2(fin2[0], oc2, w.x);
        fma2(fin2[1], oc2, w.y);
    }
    int b = n0 >> 12;
    int s = (n0 & 4095) + tt;
#pragma unroll
    for (int j = 0; j < 2; j++) {
        float f0, f1;
        unpack2(fin2[j], f0, f1);
        int ch = c0 + 2 * j;
        f0 += bo[ch]     + t_s[tt * 65 + ch];
        f1 += bo[ch + 1] + t_s[tt * 65 + ch + 1];
        out[(b * 64 + ch    ) * 4096 + s] = f0;
        out[(b * 64 + ch + 1) * 4096 + s] = f1;
    }
}

// ---------------- launch ----------------
extern "C" void kernel_launch(void* const* d_in, const int* in_sizes, int n_in,
                              void* d_out, int out_size) {
    const float* x  = (const float*)d_in[0];
    const float* w1 = (const float*)d_in[1];
    const float* b1 = (const float*)d_in[2];
    const float* w2 = (const float*)d_in[3];
    const float* b2 = (const float*)d_in[4];
    const float* wq = (const float*)d_in[5];
    const float* wk = (const float*)d_in[6];
    const float* wv = (const float*)d_in[7];
    const float* wo = (const float*)d_in[8];
    const float* bo = (const float*)d_in[9];
    float* out = (float*)d_out;

    cudaFuncSetAttribute(k_attn, cudaFuncAttributeMaxDynamicSharedMemorySize,
                         SMEM_FLOATS * (int)sizeof(float));

    k_transpose_w<<<(2 * 36864 + 255) / 256, 256>>>(w1, w2);
    k_conv<0><<<dim3(2, 32, 8), dim3(256)>>>(x, b1);
    k_conv<1><<<dim3(2, 32, 8), dim3(256)>>>(x, b1);
    k_attn<<<256, 512, SMEM_FLOATS * (int)sizeof(float)>>>(wq, wk, wv, wo, bo, b2, out);
}

// round 16
// speedup vs baseline: 1.1026x; 1.0385x over previous
#include <cuda_runtime.h>

typedef unsigned long long ull;

__device__ __forceinline__ ull pack2(float lo, float hi) {
    ull r; asm("mov.b64 %0, {%1, %2};" : "=l"(r) : "f"(lo), "f"(hi)); return r;
}
__device__ __forceinline__ void unpack2(ull v, float& lo, float& hi) {
    asm("mov.b64 {%0, %1}, %2;" : "=f"(lo), "=f"(hi) : "l"(v));
}
__device__ __forceinline__ void fma2(ull& d, ull a, ull b) {
    asm("fma.rn.f32x2 %0, %1, %2, %0;" : "+l"(d) : "l"(a), "l"(b));
}
__device__ __forceinline__ float ex2f(float x) {
    float y; asm("ex2.approx.f32 %0, %1;" : "=f"(y) : "f"(x)); return y;
}

// ---------------- scratch (no allocations allowed) ----------------
#define NTOK (2*4096)              // 8192 tokens
#define PBUF (NTOK*64)             // 524288 floats per partial buffer
__device__ float g_p[4*PBUF];      // conv1 partials (per ci-quarter)
__device__ float g_q[4*PBUF];      // conv2 partials (per ci-quarter)
__device__ float g_wt1[64*9*64];   // [ci][k][(co2,s)]: pair = (co2, co2+32)
__device__ float g_wt2[64*9*64];

// ---- prep: [co][ci][3][3] -> [ci][k][(co2,s)] where pair = (co2, co2+32) ----
__global__ void k_transpose_w(const float* __restrict__ w1, const float* __restrict__ w2) {
    int i = blockIdx.x * blockDim.x + threadIdx.x;
    if (i >= 2 * 36864) return;
    const float* w = (i < 36864) ? w1 : w2;
    float* dst     = (i < 36864) ? g_wt1 : g_wt2;
    int o   = (i < 36864) ? i : (i - 36864);
    int ci  = o / 576;
    int rem = o - ci * 576;
    int kk  = rem >> 6;
    int qq  = rem & 63;
    int co2 = qq >> 1;
    int s   = qq & 1;
    dst[o] = w[(s * 32 + co2) * 576 + ci * 9 + kk];
}

// ---------------- partial conv3x3: 16 ci x 64 co, tile 2 rows x 64 px ----------------
// 512 threads = 32 co-pairs x 8 px-groups x 2 rows; thread: 1 row x 8 px x (co2,co2+32).
// grid (1,32,8): z = b*4 + quarter. SINGLE WAVE: 256 blocks, 2 resident/SM, 32 warps/SM.
// SRC=0: in = x (NCHW); out = g_p[quarter]. SRC=1: in = relu(Σ4 g_p + b1); out = g_q[quarter]
#define IN_CI_STRIDE 276   // 4 rows * 68 + pad; 16B-aligned, %32 = 20 (conflict-free)
template<int SRC>
__global__ void __launch_bounds__(512, 2) k_conv(const float* __restrict__ in_x,
                                                 const float* __restrict__ in_bias) {
    const float* __restrict__ wt = (SRC == 0) ? g_wt1 : g_wt2;

    __shared__ float w_s[16 * 576];              // 36.9 KB
    __shared__ float in_s[16 * IN_CI_STRIDE];    // 17.7 KB; [ci][r*68 + xx], r<4, xx<66

    const int tid = threadIdx.x;
    const int co2 = tid & 31;
    const int h   = (tid >> 5) & 7;              // 8-px group, uniform per warp
    const int rg  = tid >> 8;                    // output row 0/1, uniform per warp
    const int y0 = blockIdx.y * 2;
    const int b       = blockIdx.z >> 2;
    const int quarter = blockIdx.z & 3;

    // ---- stage weights: 16 ci x 576 = 9216 floats = 4608 float2 = 9 x 512
    {
        const float2* wsrc = (const float2*)(wt + quarter * 16 * 576);
        float2* wdst = (float2*)w_s;
#pragma unroll
        for (int i = 0; i < 9; i++)
            wdst[tid + i * 512] = wsrc[tid + i * 512];
    }
    // ---- stage inputs: 16 ci x 4 rows x 66 px = 4224 elements
    if (SRC == 0) {
        // NCHW x: xx fastest -> coalesced LDG
#pragma unroll
        for (int i = 0; i < 9; i++) {
            int e = i * 512 + tid;
            if (e < 4224) {
                int xx = e % 66;
                int t  = e / 66;                 // 0..63
                int r  = t & 3;
                int ci = t >> 2;
                int y  = y0 - 1 + r;
                int xg = xx - 1;
                float v = 0.f;
                if ((unsigned)y < 64u && (unsigned)xg < 64u)
                    v = in_x[((b * 64 + quarter * 16 + ci) * 64 + y) * 64 + xg];
                in_s[ci * IN_CI_STRIDE + r * 68 + xx] = v;
            }
        }
    } else {
        // NHWC partials: ci fastest -> coalesced
        const int ci = tid & 15;
        const float bvin = in_bias[quarter * 16 + ci];
#pragma unroll
        for (int i = 0; i < 9; i++) {
            int e = i * 512 + tid;
            if (e < 4224) {
                int t  = e >> 4;                 // 0..263
                int r  = t / 66;
                int xx = t - r * 66;
                int y  = y0 - 1 + r;
                int xg = xx - 1;
                float v = 0.f;
                if ((unsigned)y < 64u && (unsigned)xg < 64u) {
                    int idx = ((b * 64 + y) * 64 + xg) * 64 + quarter * 16 + ci;
                    float s0 = g_p[idx]          + g_p[idx + PBUF];
                    float s1 = g_p[idx + 2*PBUF] + g_p[idx + 3*PBUF];
                    v = fmaxf(s0 + s1 + bvin, 0.f);
                }
                in_s[ci * IN_CI_STRIDE + r * 68 + xx] = v;
            }
        }
    }
    __syncthreads();

    ull acc[8] = {0,0,0,0,0,0,0,0};

#pragma unroll 4
    for (int ci = 0; ci < 16; ci++) {
        const ull* wp = (const ull*)(w_s + ci * 576) + co2;
        ull w2[9];
#pragma unroll
        for (int k = 0; k < 9; k++) w2[k] = wp[k * 32];

        // input rows rg..rg+2 feed output row y0+rg; px window xx = h*8 .. h*8+9
        const float* ibase = in_s + ci * IN_CI_STRIDE + rg * 68 + h * 8;
#pragma unroll
        for (int dy = 0; dy < 3; dy++) {
            const float* row = ibase + dy * 68;
            // half 1: px p = 0..3 (inputs xx 0..5)
            {
                float4 v0 = *(const float4*)(row);       // broadcast
                float2 v1 = *(const float2*)(row + 4);   // broadcast
                ull d[6];
                d[0] = pack2(v0.x, v0.x); d[1] = pack2(v0.y, v0.y);
                d[2] = pack2(v0.z, v0.z); d[3] = pack2(v0.w, v0.w);
                d[4] = pack2(v1.x, v1.x); d[5] = pack2(v1.y, v1.y);
#pragma unroll
                for (int p = 0; p < 4; p++) {
                    fma2(acc[p], w2[dy*3+0], d[p]);
                    fma2(acc[p], w2[dy*3+1], d[p+1]);
                    fma2(acc[p], w2[dy*3+2], d[p+2]);
                }
            }
            // half 2: px p = 4..7 (inputs xx 4..9)
            {
                float2 v0 = *(const float2*)(row + 4);   // broadcast
                float4 v1 = *(const float4*)(row + 6);   // broadcast
                ull d[6];
                d[0] = pack2(v0.x, v0.x); d[1] = pack2(v0.y, v0.y);
                d[2] = pack2(v1.x, v1.x); d[3] = pack2(v1.y, v1.y);
                d[4] = pack2(v1.z, v1.z); d[5] = pack2(v1.w, v1.w);
#pragma unroll
                for (int p = 0; p < 4; p++) {
                    fma2(acc[4+p], w2[dy*3+0], d[p]);
                    fma2(acc[4+p], w2[dy*3+1], d[p+1]);
                    fma2(acc[4+p], w2[dy*3+2], d[p+2]);
                }
            }
        }
    }

    float* __restrict__ out = ((SRC == 0) ? g_p : g_q) + quarter * PBUF;
    int y = y0 + rg;
    int base = ((b * 64 + y) * 64 + h * 8) * 64;
#pragma unroll
    for (int p = 0; p < 8; p++) {
        float lo, hi;
        unpack2(acc[p], lo, hi);
        out[base + p * 64 + co2]      = lo;      // lanes = co2 -> coalesced
        out[base + p * 64 + co2 + 32] = hi;
    }
}

// ---------------- attention: 32 tokens/block, 512 threads (R13 exact, best=26.2us) ----
#define W_STRIDE 66
#define OFF_WQ 0
#define OFF_WK 4224
#define OFF_WV 8448
#define OFF_WO 12672
#define OFF_T  16896               // [32][65]
#define OFF_KV 18976               // float2 [32][65]
#define OFF_O  23136               // [32][65]
#define OFF_SQ 25216               // [16][33]
#define OFF_SK 25744
#define SMEM_FLOATS 26272          // 105088 bytes

__global__ void __launch_bounds__(512) k_attn(
    const float* __restrict__ wq, const float* __restrict__ wk,
    const float* __restrict__ wv, const float* __restrict__ wo,
    const float* __restrict__ bo, const float* __restrict__ b2,
    float* __restrict__ out)
{
    extern __shared__ float sm[];
    float*  wq_s = sm + OFF_WQ;    // [l][c], stride 66
    float*  wk_s = sm + OFF_WK;
    float*  wv_s = sm + OFF_WV;
    float*  wo_s = sm + OFF_WO;
    float*  t_s  = sm + OFF_T;
    float2* kv_s = (float2*)(sm + OFF_KV);
    float*  o_s  = sm + OFF_O;
    float*  sq_s = sm + OFF_SQ;
    float*  sk_s = sm + OFF_SK;

    int tid = threadIdx.x;
    int n0  = blockIdx.x * 32;

#pragma unroll
    for (int i = 0; i < 8; i++) {
        int gg = tid + i * 512;
        int c = gg >> 6, l = gg & 63;
        wq_s[l * 66 + c] = wq[gg];
        wk_s[l * 66 + c] = wk[gg];
        wv_s[l * 66 + c] = wv[gg];
        wo_s[l * 66 + c] = wo[gg];
    }
#pragma unroll
    for (int i = 0; i < 4; i++) {
        int gg = tid + i * 512;
        int idx = n0 * 64 + gg;
        float s0 = g_q[idx]          + g_q[idx + PBUF];
        float s1 = g_q[idx + 2*PBUF] + g_q[idx + 3*PBUF];
        t_s[(gg >> 6) * 65 + (gg & 63)] = s0 + s1 + b2[gg & 63];
    }
    __syncthreads();

    const int tt = tid & 31;
    const int cg = tid >> 5;       // 0..15 (uniform per warp)
    const int c0 = cg * 4;

    // phase 1: q/k/v matvecs (4 channels each)
    ull q2[2] = {0,0}, k2[2] = {0,0}, v2[2] = {0,0};
    const float* trow = t_s + tt * 65;
#pragma unroll 4
    for (int l = 0; l < 64; l++) {
        float tl = trow[l];
        ull tl2 = pack2(tl, tl);
        const ull* wql = (const ull*)(wq_s + l * 66 + c0);
        const ull* wkl = (const ull*)(wk_s + l * 66 + c0);
        const ull* wvl = (const ull*)(wv_s + l * 66 + c0);
        fma2(q2[0], tl2, wql[0]); fma2(q2[1], tl2, wql[1]);
        fma2(k2[0], tl2, wkl[0]); fma2(k2[1], tl2, wkl[1]);
        fma2(v2[0], tl2, wvl[0]); fma2(v2[1], tl2, wvl[1]);
    }
    float q[4], kk[4], vv[4];
    unpack2(q2[0], q[0], q[1]);  unpack2(q2[1], q[2], q[3]);
    unpack2(k2[0], kk[0], kk[1]); unpack2(k2[1], kk[2], kk[3]);
    unpack2(v2[0], vv[0], vv[1]); unpack2(v2[1], vv[2], vv[3]);

    float sq = 0.f, sk = 0.f;
#pragma unroll
    for (int j = 0; j < 4; j++) { sq = fmaf(q[j], q[j], sq); sk = fmaf(kk[j], kk[j], sk); }
    sq_s[cg * 33 + tt] = sq;
    sk_s[cg * 33 + tt] = sk;
    __syncthreads();
    sq = 0.f; sk = 0.f;
#pragma unroll
    for (int m = 0; m < 16; m++) { sq += sq_s[m * 33 + tt]; sk += sk_s[m * 33 + tt]; }
    const float LOG2E = 1.4426950408889634f;
    float invq = LOG2E / fmaxf(sqrtf(sq), 1e-12f);
    float invk = 1.0f  / fmaxf(sqrtf(sk), 1e-12f);
#pragma unroll
    for (int j = 0; j < 4; j++) {
        q[j] *= invq;                                      // stays in regs
        kv_s[tt * 65 + c0 + j] = make_float2(kk[j] * invk, vv[j]);
    }
    __syncthreads();

    // phase 2: rank-1 softmax; packed num/den: fma2(nd, {e,e}, {v_d, 1})
    ull nd[4] = {0,0,0,0};
    const float2* kvrow = kv_s + tt * 65;
#pragma unroll 4
    for (int d = 0; d < 64; d++) {
        float2 kv = kvrow[d];
        ull vd2 = pack2(kv.y, 1.0f);
#pragma unroll
        for (int j = 0; j < 4; j++) {
            float e = ex2f(q[j] * kv.x);
            fma2(nd[j], pack2(e, e), vd2);
        }
    }
#pragma unroll
    for (int j = 0; j < 4; j++) {
        float num, den;
        unpack2(nd[j], num, den);
        o_s[tt * 65 + c0 + j] = __fdividef(num, den);
    }
    __syncthreads();

    // phase 3: Wo projection + bias + residual; coalesced NCHW stores
    ull fin2[2] = {0,0};
    const float* orow = o_s + tt * 65;
#pragma unroll 4
    for (int c = 0; c < 64; c++) {
        float oc = orow[c];
        ull oc2 = pack2(oc, oc);
        const ull* wol = (const ull*)(wo_s + c * 66 + c0);
        fma2(fin2[0], oc2, wol[0]);
        fma2(fin2[1], oc2, wol[1]);
    }
    int b = n0 >> 12;
    int s = (n0 & 4095) + tt;
#pragma unroll
    for (int j = 0; j < 2; j++) {
        float f0, f1;
        unpack2(fin2[j], f0, f1);
        int ch = c0 + 2 * j;
        f0 += bo[ch]     + t_s[tt * 65 + ch];
        f1 += bo[ch + 1] + t_s[tt * 65 + ch + 1];
        out[(b * 64 + ch    ) * 4096 + s] = f0;
        out[(b * 64 + ch + 1) * 4096 + s] = f1;
    }
}

// ---------------- launch ----------------
extern "C" void kernel_launch(void* const* d_in, const int* in_sizes, int n_in,
                              void* d_out, int out_size) {
    const float* x  = (const float*)d_in[0];
    const float* w1 = (const float*)d_in[1];
    const float* b1 = (const float*)d_in[2];
    const float* w2 = (const float*)d_in[3];
    const float* b2 = (const float*)d_in[4];
    const float* wq = (const float*)d_in[5];
    const float* wk = (const float*)d_in[6];
    const float* wv = (const float*)d_in[7];
    const float* wo = (const float*)d_in[8];
    const float* bo = (const float*)d_in[9];
    float* out = (float*)d_out;

    cudaFuncSetAttribute(k_attn, cudaFuncAttributeMaxDynamicSharedMemorySize,
                         SMEM_FLOATS * (int)sizeof(float));

    k_transpose_w<<<(2 * 36864 + 255) / 256, 256>>>(w1, w2);
    k_conv<0><<<dim3(1, 32, 8), dim3(512)>>>(x, b1);
    k_conv<1><<<dim3(1, 32, 8), dim3(512)>>>(x, b1);
    k_attn<<<256, 512, SMEM_FLOATS * (int)sizeof(float)>>>(wq, wk, wv, wo, bo, b2, out);
}